// round 14
// baseline (speedup 1.0000x reference)
#include <cuda_runtime.h>
#include <cstdint>

// ============================================================================
// y[m,o] = fq_tok(x)[m,:] . fq_ch(w)[o,:] + b[o]
//   fq value = q * s, q integer in [-128,127]:
//   y[m,o] = sx[m]*sw[o]*(sum_k qx[m,k]*qw[o,k]) + b[o]
// Exact int8 GEMM. sm_103 family-PTX (tcgen05 rejected).
// Calibrated: tensor pipe 64 MACs/SMSP/cyc; dp4a 128 MACs/SMSP/cyc (1/SMSP
// issue). Hybrid CTAs lose ~27% pipe time to heterogeneous-warp barrier
// coupling (r6-r13). Round 14: WHOLE-CTA SPECIALIZATION with guaranteed
// per-SM pairing:
//   296 persistent CTAs; role = per-SM arrival parity (%smid atomic) ->
//   exactly 1 tensor CTA + 1 dp4a CTA per SM. Each pulls half-tiles from its
//   role's global work queue (reset by quant kernel each launch).
//   tensor CTA: rows 0-47 of each tile  (8 warps, 48x16 warp tiles).
//   dp4a  CTA: rows 48-127 of each tile (5x8 outputs/thread, r6 loop shape).
// M = 8192 (derived), N = 4096, K = 4096.
// ============================================================================

#define MAX_M 8192
#define NN 4096
#define KK 4096
#define TS 48                      // tensor rows per tile
#define DS 80                      // dp4a rows per tile

__device__ int8_t g_qx[(size_t)MAX_M * KK];   // 32 MB
__device__ int8_t g_qw[(size_t)NN * KK];      // 16 MB
__device__ float g_sx[MAX_M];
__device__ float g_sw[NN];
__device__ unsigned int g_slot[256];          // per-SM arrival counters (parity; no reset needed)
__device__ int g_qt;                          // tensor work queue head
__device__ int g_qd;                          // dp4a work queue head

// ---------------------------------------------------------------------------
// PTX helpers (family-portable, sm_80+ baseline ISA)
// ---------------------------------------------------------------------------
__device__ __forceinline__ uint32_t smem_u32(const void* p) {
    uint32_t a;
    asm("{ .reg .u64 t; cvta.to.shared.u64 t, %1; cvt.u32.u64 %0, t; }" : "=r"(a) : "l"(p));
    return a;
}

__device__ __forceinline__ uint32_t smid_u32() {
    uint32_t s;
    asm("mov.u32 %0, %%smid;" : "=r"(s));
    return s;
}

#define CP_ASYNC16(smem, gptr) \
    asm volatile("cp.async.cg.shared.global [%0], [%1], 16;" \
        :: "r"((uint32_t)(smem)), "l"(gptr) : "memory")
#define CP_COMMIT() asm volatile("cp.async.commit_group;" ::: "memory")
#define CP_WAIT(n)  asm volatile("cp.async.wait_group %0;" :: "n"(n) : "memory")

#define LDSM_X4(r0, r1, r2, r3, addr) \
    asm volatile("ldmatrix.sync.aligned.m8n8.x4.shared.b16 {%0,%1,%2,%3}, [%4];" \
        : "=r"(r0), "=r"(r1), "=r"(r2), "=r"(r3) : "r"((uint32_t)(addr)))

#define MMA_S8(d, a0, a1, a2, a3, b0, b1) \
    asm volatile("mma.sync.aligned.m16n8k32.row.col.s32.s8.s8.s32 " \
        "{%0,%1,%2,%3},{%4,%5,%6,%7},{%8,%9},{%0,%1,%2,%3};" \
        : "+r"((d)[0]), "+r"((d)[1]), "+r"((d)[2]), "+r"((d)[3]) \
        : "r"(a0), "r"(a1), "r"(a2), "r"(a3), "r"(b0), "r"(b1))

// ---------------------------------------------------------------------------
// Kernel 1: fused per-row symmetric fake-quant; block 0 also resets queues.
// ---------------------------------------------------------------------------
__global__ __launch_bounds__(256) void quant_rows(const float* __restrict__ x,
                                                  const float* __restrict__ w,
                                                  int M) {
    const int bid = blockIdx.x;
    if (bid == 0 && threadIdx.x == 0) {
        g_qt = 0;
        g_qd = 0;
    }

    const bool is_x = bid < M;
    const int row = is_x ? bid : bid - M;
    const float* in = is_x ? x : w;
    int8_t* qout = is_x ? g_qx : g_qw;
    float* sout = is_x ? g_sx : g_sw;

    const int t = threadIdx.x;
    const float4* src = reinterpret_cast<const float4*>(in) + (size_t)row * (KK / 4);

    float4 v[4];
    float am = 0.f;
#pragma unroll
    for (int j = 0; j < 4; j++) {
        v[j] = src[t + j * 256];
        am = fmaxf(am, fmaxf(fmaxf(fabsf(v[j].x), fabsf(v[j].y)),
                             fmaxf(fabsf(v[j].z), fabsf(v[j].w))));
    }
#pragma unroll
    for (int o = 16; o; o >>= 1) am = fmaxf(am, __shfl_xor_sync(0xffffffffu, am, o));

    __shared__ float s_red[8];
    __shared__ float s_scale;
    if ((t & 31) == 0) s_red[t >> 5] = am;
    __syncthreads();
    if (t < 8) {
        float a = s_red[t];
#pragma unroll
        for (int o = 4; o; o >>= 1) a = fmaxf(a, __shfl_xor_sync(0xffu, a, o));
        if (t == 0) {
            float sc = fmaxf(a / 127.0f, 1e-8f);
            s_scale = sc;
            sout[row] = sc;
        }
    }
    __syncthreads();
    const float inv = 1.0f / s_scale;

    uint32_t* qrow = reinterpret_cast<uint32_t*>(qout + (size_t)row * KK);
#pragma unroll
    for (int j = 0; j < 4; j++) {
        int q0 = min(max(__float2int_rn(v[j].x * inv), -128), 127);
        int q1 = min(max(__float2int_rn(v[j].y * inv), -128), 127);
        int q2 = min(max(__float2int_rn(v[j].z * inv), -128), 127);
        int q3 = min(max(__float2int_rn(v[j].w * inv), -128), 127);
        qrow[t + j * 256] = (uint32_t)(q0 & 0xff) | ((uint32_t)(q1 & 0xff) << 8) |
                            ((uint32_t)(q2 & 0xff) << 16) | ((uint32_t)q3 << 24);
    }
}

// ---------------------------------------------------------------------------
// Kernel 2: role-specialized persistent GEMM CTAs.
//   BK=64, 4-stage cp.async, 80B-padded smem rows, 256 threads, 2 CTAs/SM.
// ---------------------------------------------------------------------------
#define STAGES 4
#define STAGE_T ((TS + 128) * 80)   // 14080 (A 48 rows + B 128 rows)
#define STAGE_D ((DS + 128) * 80)   // 16640 (A 80 rows + B 128 rows)
#define DYN_SMEM (STAGES * STAGE_D) // 66560

__global__ __launch_bounds__(256, 2) void gemm_split(const float* __restrict__ bias,
                                                     float* __restrict__ out,
                                                     int n_tiles) {
    constexpr int KT = KK / 64;   // 64 K-iterations per tile

    extern __shared__ char sm[];
    __shared__ float s_sw[128];
    __shared__ float s_bias[128];
    __shared__ int s_role;
    __shared__ int s_item;

    const int t = threadIdx.x;
    const int lane = t & 31;
    const int wid = t >> 5;

    if (t == 0)
        s_role = (int)(atomicAdd(&g_slot[smid_u32() & 255], 1u) & 1u);
    __syncthreads();
    const int role = s_role;
    const uint32_t smbase = smem_u32(sm);

    if (role == 0) {
        // =================== TENSOR CTA: rows 0-47 of each tile ==============
        // 8 warps; warp w owns cols w*16..+15, all 48 rows (3 m16 x 2 n8).
        const uint32_t a_off =
            (uint32_t)(lane & 15) * 80u + (uint32_t)(lane >> 4) * 16u;
        const uint32_t b_off =
            (uint32_t)(wid * 16 + (lane & 7) + ((lane >> 4) & 1) * 8) * 80u +
            (uint32_t)((lane >> 3) & 1) * 16u;

        while (true) {
            if (t == 0) s_item = atomicAdd(&g_qt, 1);
            CP_WAIT(0);
            __syncthreads();
            const int item = s_item;
            if (item >= n_tiles) break;

            const int m0 = (item >> 5) * 128;
            const int n0 = (item & 31) * 128;
            if (t < 128) {
                s_sw[t] = g_sw[n0 + t];
                s_bias[t] = bias[n0 + t];
            }
            const int8_t* gA = g_qx + (size_t)m0 * KK;
            const int8_t* gB = g_qw + (size_t)n0 * KK;

            auto issue = [&](int it) {
                const uint32_t sbase = smbase + (uint32_t)(it % STAGES) * STAGE_T;
                const int koff = it * 64;
#pragma unroll
                for (int c = t; c < (TS + 128) * 4; c += 256) {
                    const int row = c >> 2;
                    const int q = c & 3;
                    const uint32_t dst = sbase + (uint32_t)row * 80u + (uint32_t)q * 16u;
                    const int8_t* src = (row < TS)
                        ? gA + (size_t)row * KK + koff + q * 16
                        : gB + (size_t)(row - TS) * KK + koff + q * 16;
                    CP_ASYNC16(dst, src);
                }
            };

#pragma unroll
            for (int it = 0; it < STAGES - 1; ++it) {
                issue(it);
                CP_COMMIT();
            }

            int acc[3][2][4];
#pragma unroll
            for (int a = 0; a < 3; a++)
#pragma unroll
                for (int b = 0; b < 2; b++)
#pragma unroll
                    for (int i = 0; i < 4; i++) acc[a][b][i] = 0;

            for (int it = 0; it < KT; ++it) {
                CP_WAIT(STAGES - 2);
                __syncthreads();
                const int nit = it + STAGES - 1;
                if (nit < KT) issue(nit);
                CP_COMMIT();

                const uint32_t sa = smbase + (uint32_t)(it % STAGES) * STAGE_T;
                const uint32_t sb = sa + TS * 80;

#pragma unroll
                for (int s = 0; s < 2; ++s) {
                    uint32_t a[3][4];
#pragma unroll
                    for (int mtl = 0; mtl < 3; mtl++) {
                        LDSM_X4(a[mtl][0], a[mtl][1], a[mtl][2], a[mtl][3],
                                sa + a_off + (uint32_t)mtl * (16u * 80u) + (uint32_t)s * 32u);
                    }
                    uint32_t b0, b1, b2, b3;
                    LDSM_X4(b0, b1, b2, b3, sb + b_off + (uint32_t)s * 32u);
#pragma unroll
                    for (int mtl = 0; mtl < 3; mtl++) {
                        MMA_S8(acc[mtl][0], a[mtl][0], a[mtl][1], a[mtl][2], a[mtl][3], b0, b1);
                        MMA_S8(acc[mtl][1], a[mtl][0], a[mtl][1], a[mtl][2], a[mtl][3], b2, b3);
                    }
                }
            }

            // Epilogue (rows 0-47, cols wid*16..+15)
#pragma unroll
            for (int mtl = 0; mtl < 3; mtl++) {
                const int r0 = mtl * 16 + (lane >> 2);
                const float sx0 = g_sx[m0 + r0];
                const float sx1 = g_sx[m0 + r0 + 8];
                float* o0 = out + (size_t)(m0 + r0) * NN + n0;
                float* o1 = o0 + (size_t)8 * NN;
#pragma unroll
                for (int ntl = 0; ntl < 2; ntl++) {
                    const int lc = wid * 16 + ntl * 8 + (lane & 3) * 2;
                    const float w0 = s_sw[lc], w1 = s_sw[lc + 1];
                    const float bb0 = s_bias[lc], bb1 = s_bias[lc + 1];
                    float2 v0, v1;
                    v0.x = fmaf((float)acc[mtl][ntl][0] * sx0, w0, bb0);
                    v0.y = fmaf((float)acc[mtl][ntl][1] * sx0, w1, bb1);
                    v1.x = fmaf((float)acc[mtl][ntl][2] * sx1, w0, bb0);
                    v1.y = fmaf((float)acc[mtl][ntl][3] * sx1, w1, bb1);
                    *reinterpret_cast<float2*>(o0 + lc) = v0;
                    *reinterpret_cast<float2*>(o1 + lc) = v1;
                }
                // reset acc for next work item
#pragma unroll
                for (int ntl = 0; ntl < 2; ntl++)
#pragma unroll
                    for (int i = 0; i < 4; i++) acc[mtl][ntl][i] = 0;
            }
        }
    } else {
        // =================== dp4a CTA: rows 48-127 of each tile ==============
        // Thread (tr 0..15, tc 0..15): local rows tr*5..+4, cols {tc+16c, c<8}.
        const int tr = t >> 4;
        const int tc = t & 15;

        while (true) {
            if (t == 0) s_item = atomicAdd(&g_qd, 1);
            CP_WAIT(0);
            __syncthreads();
            const int item = s_item;
            if (item >= n_tiles) break;

            const int m0 = (item >> 5) * 128;
            const int n0 = (item & 31) * 128;
            if (t < 128) {
                s_sw[t] = g_sw[n0 + t];
                s_bias[t] = bias[n0 + t];
            }
            const int8_t* gA = g_qx + (size_t)(m0 + TS) * KK;   // rows 48-127
            const int8_t* gB = g_qw + (size_t)n0 * KK;

            auto issue = [&](int it) {
                const uint32_t sbase = smbase + (uint32_t)(it % STAGES) * STAGE_D;
                const int koff = it * 64;
#pragma unroll
                for (int c = t; c < (DS + 128) * 4; c += 256) {
                    const int row = c >> 2;
                    const int q = c & 3;
                    const uint32_t dst = sbase + (uint32_t)row * 80u + (uint32_t)q * 16u;
                    const int8_t* src = (row < DS)
                        ? gA + (size_t)row * KK + koff + q * 16
                        : gB + (size_t)(row - DS) * KK + koff + q * 16;
                    CP_ASYNC16(dst, src);
                }
            };

#pragma unroll
            for (int it = 0; it < STAGES - 1; ++it) {
                issue(it);
                CP_COMMIT();
            }

            int acc[5][8];
#pragma unroll
            for (int r = 0; r < 5; r++)
#pragma unroll
                for (int c = 0; c < 8; c++) acc[r][c] = 0;

            const uint32_t a_base = (uint32_t)(tr * 5) * 80u;
            const uint32_t b_base = (uint32_t)tc * 80u;

            for (int it = 0; it < KT; ++it) {
                CP_WAIT(STAGES - 2);
                __syncthreads();
                const int nit = it + STAGES - 1;
                if (nit < KT) issue(nit);
                CP_COMMIT();

                const uint32_t sa = smbase + (uint32_t)(it % STAGES) * STAGE_D;
                const uint32_t sb = sa + DS * 80;

#pragma unroll
                for (int g = 0; g < 4; g++) {
                    const uint32_t go = (uint32_t)g * 16u;
                    uint4 a4[5];
#pragma unroll
                    for (int r = 0; r < 5; r++) {
                        a4[r] = *reinterpret_cast<const uint4*>(
                            sm + (sa - smbase) + a_base + (uint32_t)r * 80u + go);
                    }
#pragma unroll
                    for (int c = 0; c < 8; c++) {
                        const uint4 bv = *reinterpret_cast<const uint4*>(
                            sm + (sb - smbase) + b_base + (uint32_t)c * (16u * 80u) + go);
#pragma unroll
                        for (int r = 0; r < 5; r++) {
                            int v = __dp4a((int)a4[r].x, (int)bv.x, acc[r][c]);
                            v = __dp4a((int)a4[r].y, (int)bv.y, v);
                            v = __dp4a((int)a4[r].z, (int)bv.z, v);
                            acc[r][c] = __dp4a((int)a4[r].w, (int)bv.w, v);
                        }
                    }
                }
            }

            // Epilogue (global rows m0+48+tr*5+r, cols {tc+16c})
#pragma unroll
            for (int r = 0; r < 5; r++) {
                const int row = m0 + TS + tr * 5 + r;
                const float sxv = g_sx[row];
                float* orow = out + (size_t)row * NN + n0;
#pragma unroll
                for (int c = 0; c < 8; c++) {
                    const int lc = tc + 16 * c;
                    orow[lc] = fmaf((float)acc[r][c] * sxv, s_sw[lc], s_bias[lc]);
                }
            }
        }
    }
}

// ---------------------------------------------------------------------------
// Launch
// ---------------------------------------------------------------------------
extern "C" void kernel_launch(void* const* d_in, const int* in_sizes, int n_in,
                              void* d_out, int out_size) {
    const float* x = (const float*)d_in[0];   // [M, 4096]
    const float* w = (const float*)d_in[1];   // [4096, 4096]
    const float* b = (const float*)d_in[2];   // [4096]
    float* out = (float*)d_out;               // [M, 4096]

    const int M = in_sizes[0] / KK;           // 8192
    const int n_tiles = (M / 128) * (NN / 128);   // 2048

    quant_rows<<<M + NN, 256>>>(x, w, M);     // also resets g_qt/g_qd

    cudaFuncSetAttribute(gemm_split, cudaFuncAttributeMaxDynamicSharedMemorySize,
                         DYN_SMEM);

    gemm_split<<<296, 256, DYN_SMEM>>>(b, out, n_tiles);
}

// round 15
// speedup vs baseline: 1.2152x; 1.2152x over previous
#include <cuda_runtime.h>
#include <cstdint>

// ============================================================================
// y[m,o] = fq_tok(x)[m,:] . fq_ch(w)[o,:] + b[o]
//   fq value = q * s, q integer in [-128,127]:
//   y[m,o] = sx[m]*sw[o]*(sum_k qx[m,k]*qw[o,k]) + b[o]
// Exact int8 GEMM. sm_103 family-PTX (tcgen05 rejected).
// Calibrated: tensor pipe 64 MACs/SMSP/cyc; dp4a 128 MACs/SMSP/cyc.
//   r10 hybrid (64/64 rows, one __syncthreads) loses ~26% pipe time to the
//   heterogeneous barrier; r14 (whole-CTA roles) showed pure-dp4a CTAs are
//   LDS-latency-bound without tensor warps to interleave with.
// Round 15: r10 warp mix, but the CTA's two halves are DECOUPLED:
//   separate smem regions (B duplicated, A rows disjoint), separate cp.async
//   streams, separate named barriers (bar.sync 1/2, 128 threads each).
//   warps 0-3: dp4a rows 64-127 (8x8/thread); warps 4-7: mma rows 0-63.
//   BK=64, STAGES=3 (92KB/CTA), prefetch distance 2, 2 CTAs/SM.
// M = 8192 (derived), N = 4096, K = 4096.
// ============================================================================

#define MAX_M 8192
#define NN 4096
#define KK 4096

__device__ int8_t g_qx[(size_t)MAX_M * KK];   // 32 MB
__device__ int8_t g_qw[(size_t)NN * KK];      // 16 MB
__device__ float g_sx[MAX_M];
__device__ float g_sw[NN];

// ---------------------------------------------------------------------------
// PTX helpers (family-portable, sm_80+ baseline ISA)
// ---------------------------------------------------------------------------
__device__ __forceinline__ uint32_t smem_u32(const void* p) {
    uint32_t a;
    asm("{ .reg .u64 t; cvta.to.shared.u64 t, %1; cvt.u32.u64 %0, t; }" : "=r"(a) : "l"(p));
    return a;
}

#define CP_ASYNC16(smem, gptr) \
    asm volatile("cp.async.cg.shared.global [%0], [%1], 16;" \
        :: "r"((uint32_t)(smem)), "l"(gptr) : "memory")
#define CP_COMMIT() asm volatile("cp.async.commit_group;" ::: "memory")
#define CP_WAIT(n)  asm volatile("cp.async.wait_group %0;" :: "n"(n) : "memory")

// Half-CTA named barrier: 128 threads (4 warps) arrive on id.
#define BAR_HALF(id) \
    asm volatile("bar.sync %0, %1;" :: "r"(id), "r"(128) : "memory")

#define LDSM_X4(r0, r1, r2, r3, addr) \
    asm volatile("ldmatrix.sync.aligned.m8n8.x4.shared.b16 {%0,%1,%2,%3}, [%4];" \
        : "=r"(r0), "=r"(r1), "=r"(r2), "=r"(r3) : "r"((uint32_t)(addr)))

#define MMA_S8(d, a0, a1, a2, a3, b0, b1) \
    asm volatile("mma.sync.aligned.m16n8k32.row.col.s32.s8.s8.s32 " \
        "{%0,%1,%2,%3},{%4,%5,%6,%7},{%8,%9},{%0,%1,%2,%3};" \
        : "+r"((d)[0]), "+r"((d)[1]), "+r"((d)[2]), "+r"((d)[3]) \
        : "r"(a0), "r"(a1), "r"(a2), "r"(a3), "r"(b0), "r"(b1))

// ---------------------------------------------------------------------------
// Kernel 1: fused per-row symmetric fake-quant for BOTH x and w -> int8+scale.
// ---------------------------------------------------------------------------
__global__ __launch_bounds__(256) void quant_rows(const float* __restrict__ x,
                                                  const float* __restrict__ w,
                                                  int M) {
    const int bid = blockIdx.x;
    const bool is_x = bid < M;
    const int row = is_x ? bid : bid - M;
    const float* in = is_x ? x : w;
    int8_t* qout = is_x ? g_qx : g_qw;
    float* sout = is_x ? g_sx : g_sw;

    const int t = threadIdx.x;
    const float4* src = reinterpret_cast<const float4*>(in) + (size_t)row * (KK / 4);

    float4 v[4];
    float am = 0.f;
#pragma unroll
    for (int j = 0; j < 4; j++) {
        v[j] = src[t + j * 256];
        am = fmaxf(am, fmaxf(fmaxf(fabsf(v[j].x), fabsf(v[j].y)),
                             fmaxf(fabsf(v[j].z), fabsf(v[j].w))));
    }
#pragma unroll
    for (int o = 16; o; o >>= 1) am = fmaxf(am, __shfl_xor_sync(0xffffffffu, am, o));

    __shared__ float s_red[8];
    __shared__ float s_scale;
    if ((t & 31) == 0) s_red[t >> 5] = am;
    __syncthreads();
    if (t < 8) {
        float a = s_red[t];
#pragma unroll
        for (int o = 4; o; o >>= 1) a = fmaxf(a, __shfl_xor_sync(0xffu, a, o));
        if (t == 0) {
            float sc = fmaxf(a / 127.0f, 1e-8f);
            s_scale = sc;
            sout[row] = sc;
        }
    }
    __syncthreads();
    const float inv = 1.0f / s_scale;

    uint32_t* qrow = reinterpret_cast<uint32_t*>(qout + (size_t)row * KK);
#pragma unroll
    for (int j = 0; j < 4; j++) {
        int q0 = min(max(__float2int_rn(v[j].x * inv), -128), 127);
        int q1 = min(max(__float2int_rn(v[j].y * inv), -128), 127);
        int q2 = min(max(__float2int_rn(v[j].z * inv), -128), 127);
        int q3 = min(max(__float2int_rn(v[j].w * inv), -128), 127);
        qrow[t + j * 256] = (uint32_t)(q0 & 0xff) | ((uint32_t)(q1 & 0xff) << 8) |
                            ((uint32_t)(q2 & 0xff) << 16) | ((uint32_t)q3 << 24);
    }
}

// ---------------------------------------------------------------------------
// Kernel 2: decoupled hybrid int8 GEMM. BM=BN=128, BK=64, 3-stage cp.async,
// 80B-padded rows, 256 threads, 2 CTAs/SM. Each CTA half owns its own smem
// region (A slice + private B copy), cp.async stream, and named barrier.
// Stage layout (30720 B): [A_t 64x80 | B_t 128x80 | A_d 64x80 | B_d 128x80]
// ---------------------------------------------------------------------------
#define STAGES 3
#define HALF_BYTES (192 * 80)           // 15360
#define STAGE_BYTES (2 * HALF_BYTES)    // 30720
#define DYN_SMEM (STAGES * STAGE_BYTES) // 92160

__global__ __launch_bounds__(256, 2) void gemm_hybrid(const float* __restrict__ bias,
                                                      float* __restrict__ out) {
    constexpr int KT = KK / 64;   // 64 main-loop iterations

    extern __shared__ char sm[];
    __shared__ float s_sw[128];
    __shared__ float s_bias[128];

    const int t = threadIdx.x;
    const int bid = blockIdx.x;
    const int mt = bid >> 5;
    const int nt = bid & 31;
    const int m0 = mt * 128;
    const int n0 = nt * 128;

    if (t < 128) {
        s_sw[t] = g_sw[n0 + t];
        s_bias[t] = bias[n0 + t];
    }
    __syncthreads();   // s_sw/s_bias visible to both halves; last full barrier

    const uint32_t smbase = smem_u32(sm);
    const int wid = t >> 5;
    const int lane = t & 31;

    if (wid >= 4) {
        // =========== TENSOR HALF (threads 128-255, barrier id 2) ============
        // Region per stage: A_t (A rows 0-63) at +0, B_t at +5120.
        const int u = t - 128;                 // 0..127
        const int8_t* gA = g_qx + (size_t)m0 * KK;
        const int8_t* gB = g_qw + (size_t)n0 * KK;

        auto issue = [&](int it) {
            const uint32_t base = smbase + (uint32_t)(it % STAGES) * STAGE_BYTES;
            const int koff = it * 64;
#pragma unroll
            for (int c = u; c < 768; c += 128) {   // 6 chunks of 16B
                const int row = c >> 2;
                const int q = c & 3;
                const uint32_t dst = base + (uint32_t)row * 80u + (uint32_t)q * 16u;
                const int8_t* src = (row < 64)
                    ? gA + (size_t)row * KK + koff + q * 16
                    : gB + (size_t)(row - 64) * KK + koff + q * 16;
                CP_ASYNC16(dst, src);
            }
        };

        issue(0); CP_COMMIT();
        issue(1); CP_COMMIT();

        const int w = wid - 4;
        const int warpM = w & 1;
        const int warpN = w >> 1;

        int acc[2][8][4];
#pragma unroll
        for (int a = 0; a < 2; a++)
#pragma unroll
            for (int b = 0; b < 8; b++)
#pragma unroll
                for (int i = 0; i < 4; i++) acc[a][b][i] = 0;

        const uint32_t a_off =
            (uint32_t)(warpM * 32 + (lane & 15)) * 80u + (uint32_t)(lane >> 4) * 16u;
        const uint32_t b_off = 64u * 80u +
            (uint32_t)(warpN * 64 + (lane & 7) + ((lane >> 4) & 1) * 8) * 80u +
            (uint32_t)((lane >> 3) & 1) * 16u;

        for (int it = 0; it < KT; ++it) {
            CP_WAIT(1);
            BAR_HALF(2);
            if (it + 2 < KT) issue(it + 2);
            CP_COMMIT();

            const uint32_t base = smbase + (uint32_t)(it % STAGES) * STAGE_BYTES;

#pragma unroll
            for (int s = 0; s < 2; ++s) {
                uint32_t a[2][4];
#pragma unroll
                for (int mtl = 0; mtl < 2; mtl++) {
                    LDSM_X4(a[mtl][0], a[mtl][1], a[mtl][2], a[mtl][3],
                            base + a_off + (uint32_t)mtl * (16u * 80u) + (uint32_t)s * 32u);
                }
#pragma unroll
                for (int np = 0; np < 4; np++) {
                    uint32_t b0, b1, b2, b3;
                    LDSM_X4(b0, b1, b2, b3,
                            base + b_off + (uint32_t)np * (16u * 80u) + (uint32_t)s * 32u);
#pragma unroll
                    for (int mtl = 0; mtl < 2; mtl++) {
                        MMA_S8(acc[mtl][2 * np + 0], a[mtl][0], a[mtl][1], a[mtl][2], a[mtl][3], b0, b1);
                        MMA_S8(acc[mtl][2 * np + 1], a[mtl][0], a[mtl][1], a[mtl][2], a[mtl][3], b2, b3);
                    }
                }
            }
        }

        // Epilogue (rows 0-63)
#pragma unroll
        for (int mtl = 0; mtl < 2; mtl++) {
            const int r0 = warpM * 32 + mtl * 16 + (lane >> 2);
            const float sx0 = g_sx[m0 + r0];
            const float sx1 = g_sx[m0 + r0 + 8];
            float* o0 = out + (size_t)(m0 + r0) * NN + n0;
            float* o1 = o0 + (size_t)8 * NN;
#pragma unroll
            for (int ntl = 0; ntl < 8; ntl++) {
                const int lc = warpN * 64 + ntl * 8 + (lane & 3) * 2;
                const float w0 = s_sw[lc], w1 = s_sw[lc + 1];
                const float bb0 = s_bias[lc], bb1 = s_bias[lc + 1];
                float2 v0, v1;
                v0.x = fmaf((float)acc[mtl][ntl][0] * sx0, w0, bb0);
                v0.y = fmaf((float)acc[mtl][ntl][1] * sx0, w1, bb1);
                v1.x = fmaf((float)acc[mtl][ntl][2] * sx1, w0, bb0);
                v1.y = fmaf((float)acc[mtl][ntl][3] * sx1, w1, bb1);
                *reinterpret_cast<float2*>(o0 + lc) = v0;
                *reinterpret_cast<float2*>(o1 + lc) = v1;
            }
        }
    } else {
        // =========== dp4a HALF (threads 0-127, barrier id 1) ================
        // Region per stage at +HALF_BYTES: A_d (A rows 64-127 at local 0-63)
        // then B_d at +5120.
        const int8_t* gA = g_qx + (size_t)(m0 + 64) * KK;
        const int8_t* gB = g_qw + (size_t)n0 * KK;

        auto issue = [&](int it) {
            const uint32_t base = smbase + (uint32_t)(it % STAGES) * STAGE_BYTES
                                + HALF_BYTES;
            const int koff = it * 64;
#pragma unroll
            for (int c = t; c < 768; c += 128) {   // 6 chunks of 16B
                const int row = c >> 2;
                const int q = c & 3;
                const uint32_t dst = base + (uint32_t)row * 80u + (uint32_t)q * 16u;
                const int8_t* src = (row < 64)
                    ? gA + (size_t)row * KK + koff + q * 16
                    : gB + (size_t)(row - 64) * KK + koff + q * 16;
                CP_ASYNC16(dst, src);
            }
        };

        issue(0); CP_COMMIT();
        issue(1); CP_COMMIT();

        // Thread (tr 0..7, tc 0..15): local A rows tr*8..+7, cols {tc+16c}.
        const int tr = t >> 4;
        const int tc = t & 15;

        int acc[8][8];
#pragma unroll
        for (int r = 0; r < 8; r++)
#pragma unroll
            for (int c = 0; c < 8; c++) acc[r][c] = 0;

        for (int it = 0; it < KT; ++it) {
            CP_WAIT(1);
            BAR_HALF(1);
            if (it + 2 < KT) issue(it + 2);
            CP_COMMIT();

            const uint32_t base = smbase + (uint32_t)(it % STAGES) * STAGE_BYTES
                                + HALF_BYTES;
            const uint32_t sb = base + 64u * 80u;

#pragma unroll
            for (int g = 0; g < 4; g++) {   // 4 groups of 16 K-bytes
                const uint32_t go = (uint32_t)g * 16u;
                uint4 a4[8];
#pragma unroll
                for (int r = 0; r < 8; r++) {
                    a4[r] = *reinterpret_cast<const uint4*>(
                        sm + (base - smbase) + (uint32_t)(tr * 8 + r) * 80u + go);
                }
#pragma unroll
                for (int c = 0; c < 8; c++) {
                    const uint4 bv = *reinterpret_cast<const uint4*>(
                        sm + (sb - smbase) + (uint32_t)(tc + 16 * c) * 80u + go);
#pragma unroll
                    for (int r = 0; r < 8; r++) {
                        int v = __dp4a((int)a4[r].x, (int)bv.x, acc[r][c]);
                        v = __dp4a((int)a4[r].y, (int)bv.y, v);
                        v = __dp4a((int)a4[r].z, (int)bv.z, v);
                        acc[r][c] = __dp4a((int)a4[r].w, (int)bv.w, v);
                    }
                }
            }
        }

        // Epilogue (rows 64-127)
#pragma unroll
        for (int r = 0; r < 8; r++) {
            const int row = m0 + 64 + tr * 8 + r;
            const float sxv = g_sx[row];
            float* orow = out + (size_t)row * NN + n0;
#pragma unroll
            for (int c = 0; c < 8; c++) {
                const int lc = tc + 16 * c;
                orow[lc] = fmaf((float)acc[r][c] * sxv, s_sw[lc], s_bias[lc]);
            }
        }
    }
}

// ---------------------------------------------------------------------------
// Launch
// ---------------------------------------------------------------------------
extern "C" void kernel_launch(void* const* d_in, const int* in_sizes, int n_in,
                              void* d_out, int out_size) {
    const float* x = (const float*)d_in[0];   // [M, 4096]
    const float* w = (const float*)d_in[1];   // [4096, 4096]
    const float* b = (const float*)d_in[2];   // [4096]
    float* out = (float*)d_out;               // [M, 4096]

    const int M = in_sizes[0] / KK;           // 8192

    quant_rows<<<M + NN, 256>>>(x, w, M);

    cudaFuncSetAttribute(gemm_hybrid, cudaFuncAttributeMaxDynamicSharedMemorySize,
                         DYN_SMEM);

    const int total_tiles = (M / 128) * (NN / 128);   // 2048
    gemm_hybrid<<<total_tiles, 256, DYN_SMEM>>>(b, out);
}

// round 16
// speedup vs baseline: 1.2658x; 1.0416x over previous
#include <cuda_runtime.h>
#include <cstdint>

// ============================================================================
// y[m,o] = fq_tok(x)[m,:] . fq_ch(w)[o,:] + b[o]
//   fq value = q * s, q integer in [-128,127]:
//   y[m,o] = sx[m]*sw[o]*(sum_k qx[m,k]*qw[o,k]) + b[o]
// Exact int8 GEMM. sm_103 family-PTX (tcgen05 rejected). Calibrated:
//   tensor pipe 64 MACs/SMSP/cyc; dp4a 128 MACs/SMSP/cyc; LDGSTS rt=8/SMSP.
//   r10 (128x128): LSU demand (512 LDGSTS x 8 = 4096 cyc/SMSP/iter-pair) ==
//   tensor pipe demand -> co-binding, 26% pipe idle. Barrier-style changes
//   (r13-r15) were null because they don't change this ratio.
// Round 16: BM=256, BN=128, 512 threads, 1 CTA/SM (regs 512x128 = full RF).
//   bytes/MAC x0.75 -> LSU 3072 < pipe 4096 per SM-iter: pipe is sole binder.
//   Same per-SMSP warp mix as r10 (2 tensor + 2 dp4a warps), same per-thread
//   shapes: tensor warps 8-15 rows 0-127 (32x64 warp tiles), dp4a warps 0-7
//   rows 128-255 (8x8 outputs/thread). BK=64, 4 stages, 80B rows.
// M = 8192 (derived), N = 4096, K = 4096.
// ============================================================================

#define MAX_M 8192
#define NN 4096
#define KK 4096

__device__ int8_t g_qx[(size_t)MAX_M * KK];   // 32 MB
__device__ int8_t g_qw[(size_t)NN * KK];      // 16 MB
__device__ float g_sx[MAX_M];
__device__ float g_sw[NN];

// ---------------------------------------------------------------------------
// PTX helpers (family-portable, sm_80+ baseline ISA)
// ---------------------------------------------------------------------------
__device__ __forceinline__ uint32_t smem_u32(const void* p) {
    uint32_t a;
    asm("{ .reg .u64 t; cvta.to.shared.u64 t, %1; cvt.u32.u64 %0, t; }" : "=r"(a) : "l"(p));
    return a;
}

#define CP_ASYNC16(smem, gptr) \
    asm volatile("cp.async.cg.shared.global [%0], [%1], 16;" \
        :: "r"((uint32_t)(smem)), "l"(gptr) : "memory")
#define CP_COMMIT() asm volatile("cp.async.commit_group;" ::: "memory")
#define CP_WAIT(n)  asm volatile("cp.async.wait_group %0;" :: "n"(n) : "memory")

#define LDSM_X4(r0, r1, r2, r3, addr) \
    asm volatile("ldmatrix.sync.aligned.m8n8.x4.shared.b16 {%0,%1,%2,%3}, [%4];" \
        : "=r"(r0), "=r"(r1), "=r"(r2), "=r"(r3) : "r"((uint32_t)(addr)))

#define MMA_S8(d, a0, a1, a2, a3, b0, b1) \
    asm volatile("mma.sync.aligned.m16n8k32.row.col.s32.s8.s8.s32 " \
        "{%0,%1,%2,%3},{%4,%5,%6,%7},{%8,%9},{%0,%1,%2,%3};" \
        : "+r"((d)[0]), "+r"((d)[1]), "+r"((d)[2]), "+r"((d)[3]) \
        : "r"(a0), "r"(a1), "r"(a2), "r"(a3), "r"(b0), "r"(b1))

// ---------------------------------------------------------------------------
// Kernel 1: fused per-row symmetric fake-quant for BOTH x and w -> int8+scale.
// ---------------------------------------------------------------------------
__global__ __launch_bounds__(256) void quant_rows(const float* __restrict__ x,
                                                  const float* __restrict__ w,
                                                  int M) {
    const int bid = blockIdx.x;
    const bool is_x = bid < M;
    const int row = is_x ? bid : bid - M;
    const float* in = is_x ? x : w;
    int8_t* qout = is_x ? g_qx : g_qw;
    float* sout = is_x ? g_sx : g_sw;

    const int t = threadIdx.x;
    const float4* src = reinterpret_cast<const float4*>(in) + (size_t)row * (KK / 4);

    float4 v[4];
    float am = 0.f;
#pragma unroll
    for (int j = 0; j < 4; j++) {
        v[j] = src[t + j * 256];
        am = fmaxf(am, fmaxf(fmaxf(fabsf(v[j].x), fabsf(v[j].y)),
                             fmaxf(fabsf(v[j].z), fabsf(v[j].w))));
    }
#pragma unroll
    for (int o = 16; o; o >>= 1) am = fmaxf(am, __shfl_xor_sync(0xffffffffu, am, o));

    __shared__ float s_red[8];
    __shared__ float s_scale;
    if ((t & 31) == 0) s_red[t >> 5] = am;
    __syncthreads();
    if (t < 8) {
        float a = s_red[t];
#pragma unroll
        for (int o = 4; o; o >>= 1) a = fmaxf(a, __shfl_xor_sync(0xffu, a, o));
        if (t == 0) {
            float sc = fmaxf(a / 127.0f, 1e-8f);
            s_scale = sc;
            sout[row] = sc;
        }
    }
    __syncthreads();
    const float inv = 1.0f / s_scale;

    uint32_t* qrow = reinterpret_cast<uint32_t*>(qout + (size_t)row * KK);
#pragma unroll
    for (int j = 0; j < 4; j++) {
        int q0 = min(max(__float2int_rn(v[j].x * inv), -128), 127);
        int q1 = min(max(__float2int_rn(v[j].y * inv), -128), 127);
        int q2 = min(max(__float2int_rn(v[j].z * inv), -128), 127);
        int q3 = min(max(__float2int_rn(v[j].w * inv), -128), 127);
        qrow[t + j * 256] = (uint32_t)(q0 & 0xff) | ((uint32_t)(q1 & 0xff) << 8) |
                            ((uint32_t)(q2 & 0xff) << 16) | ((uint32_t)q3 << 24);
    }
}

// ---------------------------------------------------------------------------
// Kernel 2: hybrid int8 GEMM. BM=256, BN=128, BK=64, 4-stage cp.async,
// 80B-padded smem rows, 512 threads, 1 CTA/SM (full register file).
//   warps 0-7  : dp4a (fma pipe), tile rows 128-255, 8x8 per thread.
//   warps 8-15 : mma.sync (tensor), tile rows 0-127, 4Mx2N 32x64 warp tiles.
// Stage layout: A 256x80 then B 128x80 (B shared by both halves).
// ---------------------------------------------------------------------------
#define STAGES 4
#define STAGE_BYTES (384 * 80)            // 30720
#define DYN_SMEM (STAGES * STAGE_BYTES)   // 122880

__global__ __launch_bounds__(512, 1) void gemm_hybrid(const float* __restrict__ bias,
                                                      float* __restrict__ out) {
    constexpr int KT = KK / 64;   // 64 main-loop iterations

    extern __shared__ char sm[];
    __shared__ float s_sw[128];
    __shared__ float s_bias[128];

    const int t = threadIdx.x;
    const int bid = blockIdx.x;
    const int mt = bid >> 5;      // 32 n-tiles per m-tile row
    const int nt = bid & 31;
    const int m0 = mt * 256;
    const int n0 = nt * 128;

    if (t < 128) {
        s_sw[t] = g_sw[n0 + t];
        s_bias[t] = bias[n0 + t];
    }

    const int8_t* gA = g_qx + (size_t)m0 * KK;
    const int8_t* gB = g_qw + (size_t)n0 * KK;
    const uint32_t smbase = smem_u32(sm);

    // cp.async mapping: 1536 chunks (384 rows x 4), 3 per thread.
    auto issue = [&](int it) {
        const uint32_t base = smbase + (uint32_t)(it % STAGES) * STAGE_BYTES;
        const int koff = it * 64;
#pragma unroll
        for (int j = 0; j < 3; j++) {
            const int c = t + j * 512;
            const int row = c >> 2;
            const int q = c & 3;
            const uint32_t dst = base + (uint32_t)row * 80u + (uint32_t)q * 16u;
            const int8_t* src = (row < 256)
                ? gA + (size_t)row * KK + koff + q * 16
                : gB + (size_t)(row - 256) * KK + koff + q * 16;
            CP_ASYNC16(dst, src);
        }
    };

#pragma unroll
    for (int it = 0; it < STAGES - 1; ++it) {
        issue(it);
        CP_COMMIT();
    }

    const int wid = t >> 5;
    const int lane = t & 31;

    if (wid >= 8) {
        // ===== Tensor warps: rows 0-127, 4(M) x 2(N) grid, warp tile 32x64 ===
        const int w = wid - 8;
        const int warpM = w & 3;     // 0..3 -> rows warpM*32..+31
        const int warpN = w >> 2;    // 0..1 -> cols warpN*64..+63

        int acc[2][8][4];
#pragma unroll
        for (int a = 0; a < 2; a++)
#pragma unroll
            for (int b = 0; b < 8; b++)
#pragma unroll
                for (int i = 0; i < 4; i++) acc[a][b][i] = 0;

        const uint32_t a_off =
            (uint32_t)(warpM * 32 + (lane & 15)) * 80u + (uint32_t)(lane >> 4) * 16u;
        const uint32_t b_off = 256u * 80u +
            (uint32_t)(warpN * 64 + (lane & 7) + ((lane >> 4) & 1) * 8) * 80u +
            (uint32_t)((lane >> 3) & 1) * 16u;

        for (int it = 0; it < KT; ++it) {
            CP_WAIT(STAGES - 2);
            __syncthreads();
            const int nit = it + STAGES - 1;
            if (nit < KT) issue(nit);
            CP_COMMIT();

            const uint32_t base = smbase + (uint32_t)(it % STAGES) * STAGE_BYTES;

#pragma unroll
            for (int s = 0; s < 2; ++s) {
                uint32_t a[2][4];
#pragma unroll
                for (int mtl = 0; mtl < 2; mtl++) {
                    LDSM_X4(a[mtl][0], a[mtl][1], a[mtl][2], a[mtl][3],
                            base + a_off + (uint32_t)mtl * (16u * 80u) + (uint32_t)s * 32u);
                }
#pragma unroll
                for (int np = 0; np < 4; np++) {
                    uint32_t b0, b1, b2, b3;
                    LDSM_X4(b0, b1, b2, b3,
                            base + b_off + (uint32_t)np * (16u * 80u) + (uint32_t)s * 32u);
#pragma unroll
                    for (int mtl = 0; mtl < 2; mtl++) {
                        MMA_S8(acc[mtl][2 * np + 0], a[mtl][0], a[mtl][1], a[mtl][2], a[mtl][3], b0, b1);
                        MMA_S8(acc[mtl][2 * np + 1], a[mtl][0], a[mtl][1], a[mtl][2], a[mtl][3], b2, b3);
                    }
                }
            }
        }

        // Epilogue (rows 0-127)
#pragma unroll
        for (int mtl = 0; mtl < 2; mtl++) {
            const int r0 = warpM * 32 + mtl * 16 + (lane >> 2);
            const float sx0 = g_sx[m0 + r0];
            const float sx1 = g_sx[m0 + r0 + 8];
            float* o0 = out + (size_t)(m0 + r0) * NN + n0;
            float* o1 = o0 + (size_t)8 * NN;
#pragma unroll
            for (int ntl = 0; ntl < 8; ntl++) {
                const int lc = warpN * 64 + ntl * 8 + (lane & 3) * 2;
                const float w0 = s_sw[lc], w1 = s_sw[lc + 1];
                const float bb0 = s_bias[lc], bb1 = s_bias[lc + 1];
                float2 v0, v1;
                v0.x = fmaf((float)acc[mtl][ntl][0] * sx0, w0, bb0);
                v0.y = fmaf((float)acc[mtl][ntl][1] * sx0, w1, bb1);
                v1.x = fmaf((float)acc[mtl][ntl][2] * sx1, w0, bb0);
                v1.y = fmaf((float)acc[mtl][ntl][3] * sx1, w1, bb1);
                *reinterpret_cast<float2*>(o0 + lc) = v0;
                *reinterpret_cast<float2*>(o1 + lc) = v1;
            }
        }
    } else {
        // ===== dp4a warps: rows 128-255, 8x8 outputs per thread ==============
        // Thread (tr 0..15, tc 0..15): A rows 128+tr*8..+7, cols {tc+16c, c<8}.
        // B across-lane LDS stride 80B -> conflict-free phases.
        const int tr = t >> 4;    // 0..15 (t in 0..255)
        const int tc = t & 15;    // 0..15

        int acc[8][8];
#pragma unroll
        for (int r = 0; r < 8; r++)
#pragma unroll
            for (int c = 0; c < 8; c++) acc[r][c] = 0;

        const uint32_t a_base = (uint32_t)(128 + tr * 8) * 80u;
        const uint32_t b_base = 256u * 80u + (uint32_t)tc * 80u;

        for (int it = 0; it < KT; ++it) {
            CP_WAIT(STAGES - 2);
            __syncthreads();
            const int nit = it + STAGES - 1;
            if (nit < KT) issue(nit);
            CP_COMMIT();

            const uint32_t soff = (uint32_t)((it % STAGES) * STAGE_BYTES);

#pragma unroll
            for (int g = 0; g < 4; g++) {   // 4 groups of 16 K-bytes
                const uint32_t go = (uint32_t)g * 16u;
                uint4 a4[8];
#pragma unroll
                for (int r = 0; r < 8; r++) {
                    a4[r] = *reinterpret_cast<const uint4*>(
                        sm + soff + a_base + (uint32_t)r * 80u + go);
                }
#pragma unroll
                for (int c = 0; c < 8; c++) {
                    const uint4 bv = *reinterpret_cast<const uint4*>(
                        sm + soff + b_base + (uint32_t)c * (16u * 80u) + go);
#pragma unroll
                    for (int r = 0; r < 8; r++) {
                        int v = __dp4a((int)a4[r].x, (int)bv.x, acc[r][c]);
                        v = __dp4a((int)a4[r].y, (int)bv.y, v);
                        v = __dp4a((int)a4[r].z, (int)bv.z, v);
                        acc[r][c] = __dp4a((int)a4[r].w, (int)bv.w, v);
                    }
                }
            }
        }

        // Epilogue (rows 128-255)
#pragma unroll
        for (int r = 0; r < 8; r++) {
            const int row = m0 + 128 + tr * 8 + r;
            const float sxv = g_sx[row];
            float* orow = out + (size_t)row * NN + n0;
#pragma unroll
            for (int c = 0; c < 8; c++) {
                const int lc = tc + 16 * c;
                orow[lc] = fmaf((float)acc[r][c] * sxv, s_sw[lc], s_bias[lc]);
            }
        }
    }
}

// ---------------------------------------------------------------------------
// Launch
// ---------------------------------------------------------------------------
extern "C" void kernel_launch(void* const* d_in, const int* in_sizes, int n_in,
                              void* d_out, int out_size) {
    const float* x = (const float*)d_in[0];   // [M, 4096]
    const float* w = (const float*)d_in[1];   // [4096, 4096]
    const float* b = (const float*)d_in[2];   // [4096]
    float* out = (float*)d_out;               // [M, 4096]

    const int M = in_sizes[0] / KK;           // 8192

    quant_rows<<<M + NN, 256>>>(x, w, M);

    cudaFuncSetAttribute(gemm_hybrid, cudaFuncAttributeMaxDynamicSharedMemorySize,
                         DYN_SMEM);

    const int total_tiles = (M / 256) * (NN / 128);   // 1024
    gemm_hybrid<<<total_tiles, 512, DYN_SMEM>>>(b, out);
}